// round 1
// baseline (speedup 1.0000x reference)
#include <cuda_runtime.h>
#include <stdint.h>

#define B_   4096
#define F_   1024
#define H_   256
#define C_   10
#define T_   24
#define RPB  4      // batch rows per CTA

// ---- scratch (device globals; no allocation) ----
__device__ uint32_t g_encmask[B_ * F_];     // 24-bit spike mask per (b,f)
__device__ float    g_W1T[F_ * H_];         // [f][j]
__device__ float    g_W2T[H_ * H_];         // [k][j]
__device__ float    g_W3T[H_ * H_];         // [k][j]
__device__ float    g_WliT[H_ * C_];        // [k][c]

// ============================================================
// Encoder: simulate 24-step constant-current LIF per element,
// pack spikes into a 24-bit mask.
// ============================================================
__global__ void encode_kernel(const float* __restrict__ x) {
    int idx = blockIdx.x * blockDim.x + threadIdx.x;
    if (idx >= B_ * F_) return;
    float xv = x[idx];
    float v = 0.0f;
    uint32_t m = 0;
#pragma unroll
    for (int t = 0; t < T_; t++) {
        v = v + 0.1f * (xv - v);
        if (v > 1.0f) { m |= (1u << t); v = 0.0f; }
    }
    g_encmask[idx] = m;
}

// ============================================================
// Transpose all weights so gather columns are contiguous.
// ============================================================
__global__ void transpose_kernel(const float* __restrict__ W1,
                                 const float* __restrict__ W2,
                                 const float* __restrict__ W3,
                                 const float* __restrict__ Wli) {
    int idx = blockIdx.x * blockDim.x + threadIdx.x;
    if (idx < F_ * H_) {
        int f = idx / H_, j = idx % H_;
        g_W1T[idx] = W1[j * F_ + f];
    }
    if (idx < H_ * H_) {
        int k = idx / H_, j = idx % H_;
        g_W2T[idx] = W2[j * H_ + k];
        g_W3T[idx] = W3[j * H_ + k];
    }
    if (idx < H_ * C_) {
        int k = idx / C_, c = idx % C_;
        g_WliT[idx] = Wli[c * H_ + k];
    }
}

// ============================================================
// Main persistent SNN kernel.
// 256 threads, RPB=4 rows per CTA.
// Thread (r = tid>>6, g = tid&63) owns hidden units [4g, 4g+3] of row r.
// All LIF state lives in registers across the 24 timesteps.
// Matmuls are sparse gathers of transposed weight columns (L2-resident).
// ============================================================
__global__ void __launch_bounds__(256)
snn_kernel(const float* __restrict__ b1, const float* __restrict__ b2,
           const float* __restrict__ b3, float* __restrict__ out) {
    __shared__ uint32_t s_mask[RPB][F_];   // 16 KB
    __shared__ int      s_cnt[4][RPB];
    __shared__ uint16_t s_l1[RPB][F_];     // active encoder features
    __shared__ uint16_t s_l2[RPB][H_];     // o1 spikes (binary)
    __shared__ uint16_t s_l3i[RPB][H_];    // o2 indices
    __shared__ float    s_l3v[RPB][H_];    // o2 values {1,2}
    __shared__ uint16_t s_l4i[RPB][H_];    // o3 indices
    __shared__ float    s_l4v[RPB][H_];    // o3 values {1,2,3}

    const int tid = threadIdx.x;
    const int r   = tid >> 6;
    const int g   = tid & 63;
    const int j0  = g * 4;

    // cooperative, coalesced mask load
    for (int i = tid; i < RPB * F_; i += 256) {
        int rr = i >> 10, f = i & (F_ - 1);
        s_mask[rr][f] = g_encmask[(blockIdx.x * RPB + rr) * F_ + f];
    }

    const float4 b1v = *(const float4*)(b1 + j0);
    const float4 b2v = *(const float4*)(b2 + j0);
    const float4 b3v = *(const float4*)(b3 + j0);

    float v1[4] = {0,0,0,0}, i1[4] = {0,0,0,0};
    float v2[4] = {0,0,0,0}, i2[4] = {0,0,0,0};
    float v3[4] = {0,0,0,0}, i3[4] = {0,0,0,0};

    const bool is_ro = tid < RPB * C_;
    const int  ror = tid / C_, roc = tid - ror * C_;
    float vo = 0.0f, io = 0.0f;

    __syncthreads();

    for (int t = 0; t < T_; t++) {
        if (tid < 4 * RPB) ((int*)s_cnt)[tid] = 0;
        __syncthreads();

        // ---- build encoder active lists ----
#pragma unroll
        for (int rr = 0; rr < RPB; rr++) {
#pragma unroll
            for (int kk = 0; kk < 4; kk++) {
                int f = tid + kk * 256;
                if ((s_mask[rr][f] >> t) & 1u) {
                    int p = atomicAdd(&s_cnt[0][rr], 1);
                    s_l1[rr][p] = (uint16_t)f;
                }
            }
        }
        __syncthreads();

        // ---- layer 1: gather W1T columns for active features ----
        float4 acc = b1v;
        {
            const int n = s_cnt[0][r];
            const float* Wb = g_W1T + j0;
            int e = 0;
            for (; e + 4 <= n; e += 4) {
                int f0 = s_l1[r][e], f1 = s_l1[r][e+1], f2 = s_l1[r][e+2], f3 = s_l1[r][e+3];
                float4 w0 = *(const float4*)(Wb + f0 * H_);
                float4 w1 = *(const float4*)(Wb + f1 * H_);
                float4 w2 = *(const float4*)(Wb + f2 * H_);
                float4 w3 = *(const float4*)(Wb + f3 * H_);
                acc.x += (w0.x + w1.x) + (w2.x + w3.x);
                acc.y += (w0.y + w1.y) + (w2.y + w3.y);
                acc.z += (w0.z + w1.z) + (w2.z + w3.z);
                acc.w += (w0.w + w1.w) + (w2.w + w3.w);
            }
            for (; e < n; e++) {
                float4 w = *(const float4*)(Wb + (int)s_l1[r][e] * H_);
                acc.x += w.x; acc.y += w.y; acc.z += w.z; acc.w += w.w;
            }
        }
        // LIF layer 1
        float o1v[4];
        {
            float* ap = &acc.x;
#pragma unroll
            for (int u = 0; u < 4; u++) {
                float vd = v1[u] + 0.1f * (i1[u] - v1[u]);
                float id = i1[u] * 0.8f;
                bool  z  = vd > 0.23f;
                v1[u] = z ? 0.0f : vd;
                i1[u] = id + ap[u];
                o1v[u] = z ? 1.0f : 0.0f;
                if (z) {
                    int p = atomicAdd(&s_cnt[1][r], 1);
                    s_l2[r][p] = (uint16_t)(j0 + u);
                }
            }
        }
        __syncthreads();

        // ---- layer 2: gather W2T columns for o1 spikes ----
        acc = b2v;
        {
            const int n = s_cnt[1][r];
            const float* Wb = g_W2T + j0;
            int e = 0;
            for (; e + 4 <= n; e += 4) {
                int k0 = s_l2[r][e], k1 = s_l2[r][e+1], k2 = s_l2[r][e+2], k3 = s_l2[r][e+3];
                float4 w0 = *(const float4*)(Wb + k0 * H_);
                float4 w1 = *(const float4*)(Wb + k1 * H_);
                float4 w2 = *(const float4*)(Wb + k2 * H_);
                float4 w3 = *(const float4*)(Wb + k3 * H_);
                acc.x += (w0.x + w1.x) + (w2.x + w3.x);
                acc.y += (w0.y + w1.y) + (w2.y + w3.y);
                acc.z += (w0.z + w1.z) + (w2.z + w3.z);
                acc.w += (w0.w + w1.w) + (w2.w + w3.w);
            }
            for (; e < n; e++) {
                float4 w = *(const float4*)(Wb + (int)s_l2[r][e] * H_);
                acc.x += w.x; acc.y += w.y; acc.z += w.z; acc.w += w.w;
            }
        }
        // LIF layer 2 + residual
        float o2v[4];
        {
            float* ap = &acc.x;
#pragma unroll
            for (int u = 0; u < 4; u++) {
                float vd = v2[u] + 0.1f * (i2[u] - v2[u]);
                float id = i2[u] * 0.8f;
                bool  z  = vd > 0.23f;
                v2[u] = z ? 0.0f : vd;
                i2[u] = id + ap[u];
                float o2 = (z ? 1.0f : 0.0f) + o1v[u];
                o2v[u] = o2;
                if (o2 > 0.0f) {
                    int p = atomicAdd(&s_cnt[2][r], 1);
                    s_l3i[r][p] = (uint16_t)(j0 + u);
                    s_l3v[r][p] = o2;
                }
            }
        }
        __syncthreads();

        // ---- layer 3: weighted gather of W3T columns (o2 in {1,2}) ----
        acc = b3v;
        {
            const int n = s_cnt[2][r];
            const float* Wb = g_W3T + j0;
            int e = 0;
            for (; e + 2 <= n; e += 2) {
                int k0 = s_l3i[r][e], k1 = s_l3i[r][e+1];
                float x0 = s_l3v[r][e], x1 = s_l3v[r][e+1];
                float4 w0 = *(const float4*)(Wb + k0 * H_);
                float4 w1 = *(const float4*)(Wb + k1 * H_);
                acc.x += x0 * w0.x + x1 * w1.x;
                acc.y += x0 * w0.y + x1 * w1.y;
                acc.z += x0 * w0.z + x1 * w1.z;
                acc.w += x0 * w0.w + x1 * w1.w;
            }
            for (; e < n; e++) {
                float xv = s_l3v[r][e];
                float4 w = *(const float4*)(Wb + (int)s_l3i[r][e] * H_);
                acc.x += xv * w.x; acc.y += xv * w.y;
                acc.z += xv * w.z; acc.w += xv * w.w;
            }
        }
        // LIF layer 3 + residual
        {
            float* ap = &acc.x;
#pragma unroll
            for (int u = 0; u < 4; u++) {
                float vd = v3[u] + 0.1f * (i3[u] - v3[u]);
                float id = i3[u] * 0.8f;
                bool  z  = vd > 0.23f;
                v3[u] = z ? 0.0f : vd;
                i3[u] = id + ap[u];
                float o3 = (z ? 1.0f : 0.0f) + o2v[u];
                if (o3 > 0.0f) {
                    int p = atomicAdd(&s_cnt[3][r], 1);
                    s_l4i[r][p] = (uint16_t)(j0 + u);
                    s_l4v[r][p] = o3;
                }
            }
        }
        __syncthreads();

        // ---- readout: LILinearCell (threads 0..39 own (row, class)) ----
        if (is_ro) {
            vo = vo + 0.1f * (io - vo);
            float a = 0.0f;
            const int n = s_cnt[3][ror];
            for (int e = 0; e < n; e++) {
                a += s_l4v[ror][e] * g_WliT[(int)s_l4i[ror][e] * C_ + roc];
            }
            io = io * 0.8f + a;
        }
        __syncthreads();
    }

    if (is_ro) out[(blockIdx.x * RPB + ror) * C_ + roc] = vo;
}

// ============================================================
extern "C" void kernel_launch(void* const* d_in, const int* in_sizes, int n_in,
                              void* d_out, int out_size) {
    (void)in_sizes; (void)n_in; (void)out_size;
    const float* x   = (const float*)d_in[0];
    const float* W1  = (const float*)d_in[1];
    const float* b1  = (const float*)d_in[2];
    const float* W2  = (const float*)d_in[3];
    const float* b2  = (const float*)d_in[4];
    const float* W3  = (const float*)d_in[5];
    const float* b3  = (const float*)d_in[6];
    const float* Wli = (const float*)d_in[7];
    float* out = (float*)d_out;

    encode_kernel<<<(B_ * F_ + 255) / 256, 256>>>(x);
    transpose_kernel<<<(F_ * H_ + 255) / 256, 256>>>(W1, W2, W3, Wli);
    snn_kernel<<<B_ / RPB, 256>>>(b1, b2, b3, out);
}

// round 2
// speedup vs baseline: 1.4280x; 1.4280x over previous
#include <cuda_runtime.h>
#include <stdint.h>

#define B_   4096
#define F_   1024
#define H_   256
#define C_   10
#define T_   24
#define RPB  4

// ---- transposed weights (device globals; no allocation) ----
__device__ __align__(16) float g_W1T[F_ * H_];   // [f][j]
__device__ __align__(16) float g_W2T[H_ * H_];   // [k][j]
__device__ __align__(16) float g_W3T[H_ * H_];   // [k][j]

// ---- packed f32x2 helpers (Blackwell) ----
__device__ __forceinline__ unsigned long long pk2(float lo, float hi) {
    unsigned long long r;
    asm("mov.b64 %0, {%1, %2};" : "=l"(r) : "f"(lo), "f"(hi));
    return r;
}
__device__ __forceinline__ void upk2(unsigned long long v, float& lo, float& hi) {
    asm("mov.b64 {%0, %1}, %2;" : "=f"(lo), "=f"(hi) : "l"(v));
}
__device__ __forceinline__ void addx2(unsigned long long& a, unsigned long long b) {
    asm("add.rn.f32x2 %0, %1, %2;" : "=l"(a) : "l"(a), "l"(b));
}

// per-row-group barrier (64 threads, ids 1..RPB)
#define BARG() asm volatile("bar.sync %0, 64;" :: "r"(barid) : "memory")

// ============================================================
// Tiled transpose of W1/W2/W3 into device globals.
// grid (F_/32, H_/32, 3); z selects matrix; extra x-blocks for z>0 bail.
// ============================================================
__global__ void __launch_bounds__(256) transpose_all(
    const float* __restrict__ W1, const float* __restrict__ W2,
    const float* __restrict__ W3) {
    __shared__ float tile[32][33];
    const int zi = blockIdx.z;
    const float* src = (zi == 0) ? W1 : ((zi == 1) ? W2 : W3);
    float* dst = (zi == 0) ? g_W1T : ((zi == 1) ? g_W2T : g_W3T);
    const int C = (zi == 0) ? F_ : H_;   // src cols
    const int R = H_;                     // src rows
    if ((int)(blockIdx.x * 32) >= C) return;

    const int x = blockIdx.x * 32 + threadIdx.x;
    const int y0 = blockIdx.y * 32;
#pragma unroll
    for (int dy = threadIdx.y; dy < 32; dy += 8)
        tile[dy][threadIdx.x] = src[(size_t)(y0 + dy) * C + x];
    __syncthreads();
    const int x2 = y0 + threadIdx.x;
#pragma unroll
    for (int dy = threadIdx.y; dy < 32; dy += 8)
        dst[(size_t)(blockIdx.x * 32 + dy) * R + x2] = tile[threadIdx.x][dy];
}

// ============================================================
// binary-list gather: acc += sum of W columns at prescaled byte offsets
// ============================================================
__device__ __forceinline__ void gather32(const char* __restrict__ wb,
                                         const uint32_t* __restrict__ lst, int n,
                                         unsigned long long& a01,
                                         unsigned long long& a23) {
    int e = 0;
    for (; e + 4 <= n; e += 4) {
        uint4 o = *(const uint4*)(lst + e);
        ulonglong2 w0 = *(const ulonglong2*)(wb + o.x);
        ulonglong2 w1 = *(const ulonglong2*)(wb + o.y);
        ulonglong2 w2 = *(const ulonglong2*)(wb + o.z);
        ulonglong2 w3 = *(const ulonglong2*)(wb + o.w);
        addx2(a01, w0.x); addx2(a23, w0.y);
        addx2(a01, w1.x); addx2(a23, w1.y);
        addx2(a01, w2.x); addx2(a23, w2.y);
        addx2(a01, w3.x); addx2(a23, w3.y);
    }
    for (; e < n; e++) {
        ulonglong2 w = *(const ulonglong2*)(wb + lst[e]);
        addx2(a01, w.x); addx2(a23, w.y);
    }
}

// ============================================================
// Main fused kernel: encoder + 24-step SNN + linear readout folding.
// 256 threads = RPB(4) independent 64-thread row groups (named barriers).
// Thread g of a group owns hidden units [4g, 4g+3]; LIF state in registers.
// Readout is linear -> folded into per-unit weighted spike counts q[],
// projected through Wli once at the end.
// ============================================================
__global__ void __launch_bounds__(256, 4)
snn_kernel(const float* __restrict__ x,
           const float* __restrict__ b1, const float* __restrict__ b2,
           const float* __restrict__ b3, const float* __restrict__ Wli,
           float* __restrict__ out) {
    __shared__ uint32_t s_mask[RPB][F_];                     // 16 KB
    __shared__ __align__(16) uint16_t s_l1[RPB][F_];         // 8 KB  (enc feature idx)
    __shared__ __align__(16) uint32_t s_lA[2][RPB][H_];      // 8 KB  (z1 byte offsets)
    __shared__ __align__(16) uint32_t s_lB[2][RPB][H_];      // 8 KB  (z2 byte offsets)
    __shared__ int s_cntA[RPB];
    __shared__ int s_cntL[2][2][RPB];
    __shared__ float s_part[RPB][2][C_];

    const int tid = threadIdx.x;
    const int r = tid >> 6;
    const int g = tid & 63;
    const int j0 = g * 4;
    const int barid = r + 1;
    const int row = blockIdx.x * RPB + r;
    const float* xrow = x + (size_t)row * F_;

    // ---- fused encoder: 24-bit spike masks, ILP-4 chains ----
#pragma unroll 1
    for (int m0 = 0; m0 < 16; m0 += 4) {
        float xv[4], vv[4];
        uint32_t mk[4];
#pragma unroll
        for (int j = 0; j < 4; j++) {
            xv[j] = xrow[g + 64 * (m0 + j)];
            vv[j] = 0.0f; mk[j] = 0u;
        }
#pragma unroll
        for (int t = 0; t < T_; t++) {
#pragma unroll
            for (int j = 0; j < 4; j++) {
                vv[j] = vv[j] + 0.1f * (xv[j] - vv[j]);
                if (vv[j] > 1.0f) { mk[j] |= (1u << t); vv[j] = 0.0f; }
            }
        }
#pragma unroll
        for (int j = 0; j < 4; j++) s_mask[r][g + 64 * (m0 + j)] = mk[j];
    }

    if (g == 0) {
        s_cntA[r] = 0;
        s_cntL[0][0][r] = 0; s_cntL[0][1][r] = 0;
        s_cntL[1][0][r] = 0; s_cntL[1][1][r] = 0;
    }
    BARG();

    // ---- build encoder active list for t=0 ----
#pragma unroll
    for (int m = 0; m < 16; m++) {
        int f = g + 64 * m;
        if (s_mask[r][f] & 1u) {
            int p = atomicAdd(&s_cntA[r], 1);
            s_l1[r][p] = (uint16_t)f;
        }
    }
    BARG();

    float v1[4] = {0,0,0,0}, i1[4] = {0,0,0,0};
    float v2[4] = {0,0,0,0}, i2[4] = {0,0,0,0};
    float v3[4] = {0,0,0,0}, i3[4] = {0,0,0,0};
    float q[4]  = {0,0,0,0};
    float z1f[4], z2f[4];

    // readout coefficients: coef_t = 0.9^(23-t) - 0.8^(23-t)
    float c9 = 1.0f, c8 = 1.0f;
#pragma unroll
    for (int i = 0; i < T_ - 1; i++) { c9 *= 0.9f; c8 *= 0.8f; }

    const char* W1b = (const char*)g_W1T + (size_t)j0 * 4;
    const char* W2b = (const char*)g_W2T + (size_t)j0 * 4;
    const char* W3b = (const char*)g_W3T + (size_t)j0 * 4;

    int par = 0;

#pragma unroll 1
    for (int t = 0; t < T_; t++) {
        // ================= phase 1: layer 1 =================
        {
            float4 bv = *(const float4*)(b1 + j0);
            unsigned long long a01 = pk2(bv.x, bv.y), a23 = pk2(bv.z, bv.w);
            const uint16_t* lst = s_l1[r];
            const int n = s_cntA[r];
            int e = 0;
            for (; e + 4 <= n; e += 4) {
                ushort4 o = *(const ushort4*)(lst + e);
                ulonglong2 w0 = *(const ulonglong2*)(W1b + ((uint32_t)o.x << 10));
                ulonglong2 w1 = *(const ulonglong2*)(W1b + ((uint32_t)o.y << 10));
                ulonglong2 w2 = *(const ulonglong2*)(W1b + ((uint32_t)o.z << 10));
                ulonglong2 w3 = *(const ulonglong2*)(W1b + ((uint32_t)o.w << 10));
                addx2(a01, w0.x); addx2(a23, w0.y);
                addx2(a01, w1.x); addx2(a23, w1.y);
                addx2(a01, w2.x); addx2(a23, w2.y);
                addx2(a01, w3.x); addx2(a23, w3.y);
            }
            for (; e < n; e++) {
                ulonglong2 w = *(const ulonglong2*)(W1b + ((uint32_t)lst[e] << 10));
                addx2(a01, w.x); addx2(a23, w.y);
            }
            float a[4]; upk2(a01, a[0], a[1]); upk2(a23, a[2], a[3]);
            int* cnt = &s_cntL[par][0][r];
            uint32_t* dl = s_lA[par][r];
#pragma unroll
            for (int u = 0; u < 4; u++) {
                float vd = v1[u] + 0.1f * (i1[u] - v1[u]);
                i1[u] = i1[u] * 0.8f + a[u];
                bool z = vd > 0.23f;
                v1[u] = z ? 0.0f : vd;
                z1f[u] = z ? 1.0f : 0.0f;
                if (z) { int p = atomicAdd(cnt, 1); dl[p] = (uint32_t)((j0 + u) << 10); }
            }
        }
        BARG();

        // ================= phase 2: layer 2 =================
        {
            if (g == 0) {   // safe: these are untouched during phase 2
                s_cntA[r] = 0;
                s_cntL[par ^ 1][0][r] = 0;
                s_cntL[par ^ 1][1][r] = 0;
            }
            float4 bv = *(const float4*)(b2 + j0);
            unsigned long long a01 = pk2(bv.x, bv.y), a23 = pk2(bv.z, bv.w);
            gather32(W2b, s_lA[par][r], s_cntL[par][0][r], a01, a23);
            float a[4]; upk2(a01, a[0], a[1]); upk2(a23, a[2], a[3]);
            int* cnt = &s_cntL[par][1][r];
            uint32_t* dl = s_lB[par][r];
#pragma unroll
            for (int u = 0; u < 4; u++) {
                float vd = v2[u] + 0.1f * (i2[u] - v2[u]);
                i2[u] = i2[u] * 0.8f + a[u];
                bool z = vd > 0.23f;
                v2[u] = z ? 0.0f : vd;
                z2f[u] = z ? 1.0f : 0.0f;
                if (z) { int p = atomicAdd(cnt, 1); dl[p] = (uint32_t)((j0 + u) << 10); }
            }
        }
        BARG();

        // ================= phase 3: layer 3 + readout fold + next enc list =================
        {
            float4 bv = *(const float4*)(b3 + j0);
            unsigned long long a01 = pk2(bv.x, bv.y), a23 = pk2(bv.z, bv.w);
            // o2 = z1 + z2  ->  gather both binary lists
            gather32(W3b, s_lA[par][r], s_cntL[par][0][r], a01, a23);
            gather32(W3b, s_lB[par][r], s_cntL[par][1][r], a01, a23);
            float a[4]; upk2(a01, a[0], a[1]); upk2(a23, a[2], a[3]);
            float coef = c9 - c8;
            c9 *= (1.0f / 0.9f);
            c8 *= 1.25f;
#pragma unroll
            for (int u = 0; u < 4; u++) {
                float vd = v3[u] + 0.1f * (i3[u] - v3[u]);
                i3[u] = i3[u] * 0.8f + a[u];
                bool z = vd > 0.23f;
                v3[u] = z ? 0.0f : vd;
                float o3 = (z ? 1.0f : 0.0f) + z1f[u] + z2f[u];
                q[u] = fmaf(coef, o3, q[u]);
            }
            if (t < T_ - 1) {
#pragma unroll
                for (int m = 0; m < 16; m++) {
                    int f = g + 64 * m;
                    if ((s_mask[r][f] >> (t + 1)) & 1u) {
                        int p = atomicAdd(&s_cntA[r], 1);
                        s_l1[r][p] = (uint16_t)f;
                    }
                }
            }
        }
        BARG();
        par ^= 1;
    }

    // ---- final readout: out[b][c] = sum_k q_k * Wli[c][k] ----
    const int wig = (tid >> 5) & 1;
    const int lane = tid & 31;
#pragma unroll
    for (int c = 0; c < C_; c++) {
        float4 w = *(const float4*)(Wli + c * H_ + j0);
        float s = q[0] * w.x + q[1] * w.y + q[2] * w.z + q[3] * w.w;
#pragma unroll
        for (int off = 16; off; off >>= 1)
            s += __shfl_xor_sync(0xffffffffu, s, off);
        if (lane == 0) s_part[r][wig][c] = s;
    }
    BARG();
    if (g < C_) out[(size_t)row * C_ + g] = s_part[r][0][g] + s_part[r][1][g];
}

// ============================================================
extern "C" void kernel_launch(void* const* d_in, const int* in_sizes, int n_in,
                              void* d_out, int out_size) {
    (void)in_sizes; (void)n_in; (void)out_size;
    const float* x   = (const float*)d_in[0];
    const float* W1  = (const float*)d_in[1];
    const float* b1  = (const float*)d_in[2];
    const float* W2  = (const float*)d_in[3];
    const float* b2  = (const float*)d_in[4];
    const float* W3  = (const float*)d_in[5];
    const float* b3  = (const float*)d_in[6];
    const float* Wli = (const float*)d_in[7];
    float* out = (float*)d_out;

    transpose_all<<<dim3(F_ / 32, H_ / 32, 3), dim3(32, 8)>>>(W1, W2, W3);
    snn_kernel<<<B_ / RPB, 256>>>(x, b1, b2, b3, Wli, out);
}

// round 3
// speedup vs baseline: 1.5727x; 1.1013x over previous
#include <cuda_runtime.h>
#include <stdint.h>

#define B_   4096
#define F_   1024
#define H_   256
#define C_   10
#define T_   24
#define RPB  4

// ---- transposed weights (device globals; no allocation) ----
__device__ __align__(16) float g_W1T[F_ * H_];   // [f][j]
__device__ __align__(16) float g_W2T[H_ * H_];   // [k][j]
__device__ __align__(16) float g_W3T[H_ * H_];   // [k][j]

// ---- packed f32x2 helpers (Blackwell) ----
__device__ __forceinline__ unsigned long long pk2(float lo, float hi) {
    unsigned long long r;
    asm("mov.b64 %0, {%1, %2};" : "=l"(r) : "f"(lo), "f"(hi));
    return r;
}
__device__ __forceinline__ void upk2(unsigned long long v, float& lo, float& hi) {
    asm("mov.b64 {%0, %1}, %2;" : "=f"(lo), "=f"(hi) : "l"(v));
}
__device__ __forceinline__ void addx2(unsigned long long& a, unsigned long long b) {
    asm("add.rn.f32x2 %0, %1, %2;" : "=l"(a) : "l"(a), "l"(b));
}

// per-row-group barrier (64 threads, ids 1..RPB)
#define BARG() asm volatile("bar.sync %0, 64;" :: "r"(barid) : "memory")

// ============================================================
// Tiled transpose of W1/W2/W3 into device globals.
// ============================================================
__global__ void __launch_bounds__(256) transpose_all(
    const float* __restrict__ W1, const float* __restrict__ W2,
    const float* __restrict__ W3) {
    __shared__ float tile[32][33];
    const int zi = blockIdx.z;
    const float* src = (zi == 0) ? W1 : ((zi == 1) ? W2 : W3);
    float* dst = (zi == 0) ? g_W1T : ((zi == 1) ? g_W2T : g_W3T);
    const int C = (zi == 0) ? F_ : H_;   // src cols
    const int R = H_;                     // src rows
    if ((int)(blockIdx.x * 32) >= C) return;

    const int x = blockIdx.x * 32 + threadIdx.x;
    const int y0 = blockIdx.y * 32;
#pragma unroll
    for (int dy = threadIdx.y; dy < 32; dy += 8)
        tile[dy][threadIdx.x] = src[(size_t)(y0 + dy) * C + x];
    __syncthreads();
    const int x2 = y0 + threadIdx.x;
#pragma unroll
    for (int dy = threadIdx.y; dy < 32; dy += 8)
        dst[(size_t)(blockIdx.x * 32 + dy) * R + x2] = tile[threadIdx.x][dy];
}

// ============================================================
// gather over prescaled byte offsets, 4 accumulator chains, unroll 4
// ============================================================
__device__ __forceinline__ void gatherN(const char* __restrict__ wb,
                                        const uint32_t* __restrict__ lst, int n,
                                        unsigned long long& a01, unsigned long long& a23,
                                        unsigned long long& b01, unsigned long long& b23) {
    int e = 0;
    for (; e + 4 <= n; e += 4) {
        uint4 o = *(const uint4*)(lst + e);
        ulonglong2 w0 = *(const ulonglong2*)(wb + o.x);
        ulonglong2 w1 = *(const ulonglong2*)(wb + o.y);
        ulonglong2 w2 = *(const ulonglong2*)(wb + o.z);
        ulonglong2 w3 = *(const ulonglong2*)(wb + o.w);
        addx2(a01, w0.x); addx2(a23, w0.y);
        addx2(b01, w1.x); addx2(b23, w1.y);
        addx2(a01, w2.x); addx2(a23, w2.y);
        addx2(b01, w3.x); addx2(b23, w3.y);
    }
    for (; e < n; e++) {
        ulonglong2 w = *(const ulonglong2*)(wb + lst[e]);
        addx2(a01, w.x); addx2(a23, w.y);
    }
}

// ============================================================
// Main fused kernel: encoder + 24-step SNN + folded linear readout.
// 256 threads = RPB(4) independent 64-thread row groups (named barriers).
// Thread g owns hidden units [4g,4g+3]; LIF state in registers.
// Encoder spikes stored as per-timestep 1024-bit bitmaps; per-step list
// build is an ffs-walk over 32 words (~n1 ops total, not 1024 tests).
// ============================================================
__global__ void __launch_bounds__(256, 4)
snn_kernel(const float* __restrict__ x,
           const float* __restrict__ b1, const float* __restrict__ b2,
           const float* __restrict__ b3, const float* __restrict__ Wli,
           float* __restrict__ out) {
    __shared__ uint32_t s_bits[RPB][T_][32];                 // 12 KB
    __shared__ __align__(16) uint16_t s_l1[RPB][F_];         // 8 KB
    __shared__ __align__(16) uint32_t s_lh[2][RPB][2 * H_];  // 16 KB (z1 then z2 offsets)
    __shared__ int s_cntA[RPB];
    __shared__ int s_cnt1[2][RPB];
    __shared__ int s_cnt2[2][RPB];
    __shared__ float s_part[RPB][2][C_];

    const int tid = threadIdx.x;
    const int r = tid >> 6;
    const int g = tid & 63;
    const int j0 = g * 4;
    const int barid = r + 1;
    const int row = blockIdx.x * RPB + r;
    const float* xrow = x + (size_t)row * F_;

    // ---- zero this row's bitmaps ----
    for (int i = g; i < T_ * 32; i += 64) ((uint32_t*)s_bits[r])[i] = 0;
    if (g == 0) {
        s_cntA[r] = 0;
        s_cnt1[0][r] = 0; s_cnt1[1][r] = 0;
        s_cnt2[0][r] = 0; s_cnt2[1][r] = 0;
    }
    BARG();

    // ---- fused encoder -> scatter spikes into per-step bitmaps ----
    {
        const uint32_t mybit = 1u << (g & 31);
        const int wbase = g >> 5;
#pragma unroll 1
        for (int m0 = 0; m0 < 16; m0 += 4) {
            float xv[4], vv[4];
            uint32_t mk[4];
#pragma unroll
            for (int j = 0; j < 4; j++) {
                xv[j] = xrow[g + 64 * (m0 + j)];
                vv[j] = 0.0f; mk[j] = 0u;
            }
#pragma unroll
            for (int t = 0; t < T_; t++) {
#pragma unroll
                for (int j = 0; j < 4; j++) {
                    vv[j] = vv[j] + 0.1f * (xv[j] - vv[j]);
                    if (vv[j] > 1.0f) { mk[j] |= (1u << t); vv[j] = 0.0f; }
                }
            }
#pragma unroll
            for (int j = 0; j < 4; j++) {
                uint32_t m = mk[j];
                const int w = wbase + 2 * (m0 + j);
                while (m) {
                    int t = __ffs(m) - 1; m &= m - 1;
                    atomicOr(&s_bits[r][t][w], mybit);
                }
            }
        }
    }
    BARG();

    // ---- build encoder active list for t=0 ----
    if (g < 32) {
        uint32_t w = s_bits[r][0][g];
        while (w) {
            int b = __ffs(w) - 1; w &= w - 1;
            int p = atomicAdd(&s_cntA[r], 1);
            s_l1[r][p] = (uint16_t)((g << 5) | b);
        }
    }
    BARG();

    float v1[4] = {0,0,0,0}, i1[4] = {0,0,0,0};
    float v2[4] = {0,0,0,0}, i2[4] = {0,0,0,0};
    float v3[4] = {0,0,0,0}, i3[4] = {0,0,0,0};
    float q[4]  = {0,0,0,0};
    float z1f[4], z2f[4];

    // readout coefficients: coef_t = 0.9^(23-t) - 0.8^(23-t)
    float c9 = 1.0f, c8 = 1.0f;
#pragma unroll
    for (int i = 0; i < T_ - 1; i++) { c9 *= 0.9f; c8 *= 0.8f; }

    const char* W1b = (const char*)g_W1T + (size_t)j0 * 4;
    const char* W2b = (const char*)g_W2T + (size_t)j0 * 4;
    const char* W3b = (const char*)g_W3T + (size_t)j0 * 4;

    int par = 0;

#pragma unroll 1
    for (int t = 0; t < T_; t++) {
        // ================= phase 1: layer 1 =================
        {
            float4 bv = *(const float4*)(b1 + j0);
            unsigned long long a01 = pk2(bv.x, bv.y), a23 = pk2(bv.z, bv.w);
            unsigned long long b01 = pk2(0.f, 0.f),   b23 = pk2(0.f, 0.f);
            const uint16_t* lst = s_l1[r];
            const int n = s_cntA[r];
            int e = 0;
            for (; e + 4 <= n; e += 4) {
                ushort4 o = *(const ushort4*)(lst + e);
                ulonglong2 w0 = *(const ulonglong2*)(W1b + ((uint32_t)o.x << 10));
                ulonglong2 w1 = *(const ulonglong2*)(W1b + ((uint32_t)o.y << 10));
                ulonglong2 w2 = *(const ulonglong2*)(W1b + ((uint32_t)o.z << 10));
                ulonglong2 w3 = *(const ulonglong2*)(W1b + ((uint32_t)o.w << 10));
                addx2(a01, w0.x); addx2(a23, w0.y);
                addx2(b01, w1.x); addx2(b23, w1.y);
                addx2(a01, w2.x); addx2(a23, w2.y);
                addx2(b01, w3.x); addx2(b23, w3.y);
            }
            for (; e < n; e++) {
                ulonglong2 w = *(const ulonglong2*)(W1b + ((uint32_t)lst[e] << 10));
                addx2(a01, w.x); addx2(a23, w.y);
            }
            addx2(a01, b01); addx2(a23, b23);
            float a[4]; upk2(a01, a[0], a[1]); upk2(a23, a[2], a[3]);
            int* cnt = &s_cnt1[par][r];
            uint32_t* dl = s_lh[par][r];
#pragma unroll
            for (int u = 0; u < 4; u++) {
                float vd = v1[u] + 0.1f * (i1[u] - v1[u]);
                i1[u] = i1[u] * 0.8f + a[u];
                bool z = vd > 0.23f;
                v1[u] = z ? 0.0f : vd;
                z1f[u] = z ? 1.0f : 0.0f;
                if (z) { int p = atomicAdd(cnt, 1); dl[p] = (uint32_t)((j0 + u) << 10); }
            }
        }
        BARG();

        // ================= phase 2: layer 2 =================
        {
            if (g == 0) {       // untouched during phase 2
                s_cntA[r] = 0;
                s_cnt1[par ^ 1][r] = 0;
                s_cnt2[par ^ 1][r] = 0;
            }
            float4 bv = *(const float4*)(b2 + j0);
            unsigned long long a01 = pk2(bv.x, bv.y), a23 = pk2(bv.z, bv.w);
            unsigned long long b01 = pk2(0.f, 0.f),   b23 = pk2(0.f, 0.f);
            const int nA = s_cnt1[par][r];          // stable all phase
            gatherN(W2b, s_lh[par][r], nA, a01, a23, b01, b23);
            addx2(a01, b01); addx2(a23, b23);
            float a[4]; upk2(a01, a[0], a[1]); upk2(a23, a[2], a[3]);
            int* cnt = &s_cnt2[par][r];
            uint32_t* dl = s_lh[par][r];
#pragma unroll
            for (int u = 0; u < 4; u++) {
                float vd = v2[u] + 0.1f * (i2[u] - v2[u]);
                i2[u] = i2[u] * 0.8f + a[u];
                bool z = vd > 0.23f;
                v2[u] = z ? 0.0f : vd;
                z2f[u] = z ? 1.0f : 0.0f;
                if (z) { int p = nA + atomicAdd(cnt, 1); dl[p] = (uint32_t)((j0 + u) << 10); }
            }
        }
        BARG();

        // ===== phase 3: layer 3 (one combined gather) + readout fold + next enc list =====
        {
            float4 bv = *(const float4*)(b3 + j0);
            unsigned long long a01 = pk2(bv.x, bv.y), a23 = pk2(bv.z, bv.w);
            unsigned long long b01 = pk2(0.f, 0.f),   b23 = pk2(0.f, 0.f);
            const int n = s_cnt1[par][r] + s_cnt2[par][r];   // o2 = z1 + z2
            gatherN(W3b, s_lh[par][r], n, a01, a23, b01, b23);
            addx2(a01, b01); addx2(a23, b23);
            float a[4]; upk2(a01, a[0], a[1]); upk2(a23, a[2], a[3]);
            float coef = c9 - c8;
            c9 *= (1.0f / 0.9f);
            c8 *= 1.25f;
#pragma unroll
            for (int u = 0; u < 4; u++) {
                float vd = v3[u] + 0.1f * (i3[u] - v3[u]);
                i3[u] = i3[u] * 0.8f + a[u];
                bool z = vd > 0.23f;
                v3[u] = z ? 0.0f : vd;
                float o3 = (z ? 1.0f : 0.0f) + z1f[u] + z2f[u];
                q[u] = fmaf(coef, o3, q[u]);
            }
            if (t < T_ - 1 && g < 32) {
                uint32_t w = s_bits[r][t + 1][g];
                while (w) {
                    int b = __ffs(w) - 1; w &= w - 1;
                    int p = atomicAdd(&s_cntA[r], 1);
                    s_l1[r][p] = (uint16_t)((g << 5) | b);
                }
            }
        }
        BARG();
        par ^= 1;
    }

    // ---- final readout: out[b][c] = sum_k q_k * Wli[c][k] ----
    const int wig = (tid >> 5) & 1;
    const int lane = tid & 31;
#pragma unroll
    for (int c = 0; c < C_; c++) {
        float4 w = *(const float4*)(Wli + c * H_ + j0);
        float s = q[0] * w.x + q[1] * w.y + q[2] * w.z + q[3] * w.w;
#pragma unroll
        for (int off = 16; off; off >>= 1)
            s += __shfl_xor_sync(0xffffffffu, s, off);
        if (lane == 0) s_part[r][wig][c] = s;
    }
    BARG();
    if (g < C_) out[(size_t)row * C_ + g] = s_part[r][0][g] + s_part[r][1][g];
}

// ============================================================
extern "C" void kernel_launch(void* const* d_in, const int* in_sizes, int n_in,
                              void* d_out, int out_size) {
    (void)in_sizes; (void)n_in; (void)out_size;
    const float* x   = (const float*)d_in[0];
    const float* W1  = (const float*)d_in[1];
    const float* b1  = (const float*)d_in[2];
    const float* W2  = (const float*)d_in[3];
    const float* b2  = (const float*)d_in[4];
    const float* W3  = (const float*)d_in[5];
    const float* b3  = (const float*)d_in[6];
    const float* Wli = (const float*)d_in[7];
    float* out = (float*)d_out;

    transpose_all<<<dim3(F_ / 32, H_ / 32, 3), dim3(32, 8)>>>(W1, W2, W3);
    snn_kernel<<<B_ / RPB, 256>>>(x, b1, b2, b3, Wli, out);
}